// round 16
// baseline (speedup 1.0000x reference)
#include <cuda_runtime.h>
#include <cuda_fp16.h>
#include <cstdint>

// Correlation layer via band-restricted mma.sync (m16n8k16 fp16, fp32 accum).
// out[b, di*9+dj, h, w] = sum_c f1[b,c,h,w] * f2[b,c,h+di-4,w+dj-4]
// B=8, C=256, H=64, W=128, D=81.
//
// R16 = R15 (best: R7 core + fp32-f1 A-build + f2-only cast) with:
//   1) CC=32 chunks (8 chunks, NBUF=2, same total smem) -> half the
//      wait+barrier rounds;
//   2) B tiles t0,t1 fetched by one ldmatrix.x4 (+ x2 for t2): 27 -> 18
//      LDSM ops per warp per 16-c step (R9-validated lane mapping).

#define NB 8
#define NC 256
#define NH 64
#define NW 128
#define ND 81

#define RSTRIDE 272                 // f2 smem c-row bytes (136 halves; %128==16 -> LDSM conflict-free)
#define F2RB (32 * RSTRIDE)         // per-r block: 32 c rows = 8704 B
#define OFFF1 (9 * F2RB)            // 78336
#define F1STR 132                   // f1 fp32 smem row stride in words (528 B)
#define F1SZ (32 * F1STR * 4)       // 16896 B (32 c rows)
#define BUFSZ (OFFF1 + F1SZ)        // 95232
#define NBUF 2
#define SMEM_SZ (NBUF * BUFSZ)      // 190464 B
#define NCHUNK 8
#define STAGE_W 25                  // floats per epilogue staging row

__device__ __half g_f2h[(size_t)NB * NC * NH * NW];

// ---------------- fp32 -> fp16 cast for f2 only (unpadded layout) ----------------
__global__ void cast_kernel(const float4* __restrict__ f2) {
    __half* dst = g_f2h;
    size_t i0 = (size_t)blockIdx.x * 1024 + threadIdx.x;
    #pragma unroll
    for (int k = 0; k < 4; k++) {
        size_t i = i0 + 256 * k;
        float4 v = f2[i];
        __half2 h0 = __floats2half2_rn(v.x, v.y);
        __half2 h1 = __floats2half2_rn(v.z, v.w);
        uint2 o;
        o.x = *reinterpret_cast<uint32_t*>(&h0);
        o.y = *reinterpret_cast<uint32_t*>(&h1);
        reinterpret_cast<uint2*>(dst)[i] = o;
    }
}

// ---------------- PTX helpers ----------------
__device__ __forceinline__ void cpa16(uint32_t dst, const void* src) {
    asm volatile("cp.async.ca.shared.global [%0], [%1], 16;" :: "r"(dst), "l"(src));
}
__device__ __forceinline__ void cpa8(uint32_t dst, const void* src) {
    asm volatile("cp.async.ca.shared.global [%0], [%1], 8;" :: "r"(dst), "l"(src));
}
__device__ __forceinline__ void ldsm4t(uint32_t& r0, uint32_t& r1,
                                       uint32_t& r2, uint32_t& r3, uint32_t a) {
    asm volatile("ldmatrix.sync.aligned.m8n8.x4.trans.shared.b16 {%0,%1,%2,%3}, [%4];"
                 : "=r"(r0), "=r"(r1), "=r"(r2), "=r"(r3) : "r"(a));
}
__device__ __forceinline__ void ldsm2t(uint32_t& r0, uint32_t& r1, uint32_t a) {
    asm volatile("ldmatrix.sync.aligned.m8n8.x2.trans.shared.b16 {%0,%1}, [%2];"
                 : "=r"(r0), "=r"(r1) : "r"(a));
}
__device__ __forceinline__ void mma16816(float* d, uint32_t a0, uint32_t a1,
                                         uint32_t a2, uint32_t a3,
                                         uint32_t b0, uint32_t b1) {
    asm volatile("mma.sync.aligned.m16n8k16.row.col.f32.f16.f16.f32 "
                 "{%0,%1,%2,%3}, {%4,%5,%6,%7}, {%8,%9}, {%0,%1,%2,%3};"
                 : "+f"(d[0]), "+f"(d[1]), "+f"(d[2]), "+f"(d[3])
                 : "r"(a0), "r"(a1), "r"(a2), "r"(a3), "r"(b0), "r"(b1));
}
__device__ __forceinline__ uint32_t pkh2(float lo, float hi) {
    __half2 h = __floats2half2_rn(lo, hi);
    return *reinterpret_cast<uint32_t*>(&h);
}

// ---------------- main kernel ----------------
__global__ void __launch_bounds__(256, 1)
corr_mma(const float* __restrict__ f1, float* __restrict__ out) {
    extern __shared__ char smem[];
    const uint32_t sb = (uint32_t)__cvta_generic_to_shared(smem);
    const int tid = threadIdx.x;
    const int lane = tid & 31, m = tid >> 5;    // warp = m16 w-block
    const int h = blockIdx.x, b = blockIdx.y;
    const size_t bbase = (size_t)b * NC * NH * NW;

    // Zero the f2 w-halos (cols 0-3 and 132-135 of each 272B c-row) in both
    // buffers; the 8B copies only ever write bytes [8, 264).
    for (int i = tid; i < NBUF * 9 * 32; i += 256) {
        int buf = i / 288, rr = i % 288;
        char* row = smem + buf * BUFSZ + rr * RSTRIDE;
        *reinterpret_cast<uint64_t*>(row) = 0ull;
        *reinterpret_cast<uint64_t*>(row + 264) = 0ull;
    }
    __syncthreads();

    float acc[9][3][4];
    #pragma unroll
    for (int r = 0; r < 9; r++)
        #pragma unroll
        for (int t = 0; t < 3; t++)
            #pragma unroll
            for (int k = 0; k < 4; k++)
                acc[r][t][k] = 0.0f;

    // A fragment source (f1 fp32 in smem, [k][w] stride F1STR words):
    // rows 2tig(+1), 2tig+8(+1) within a 16-k step; cols 16m+gid, +8.
    const int gid = lane >> 2, tig = lane & 3;
    const uint32_t a_word0 = (uint32_t)(2 * tig) * F1STR + 16 * m + gid;
    // B (.trans): x4 covers tiles at padded cols 16m, 16m+8 (lanes 0-15 k-rows
    // at col base, 16-31 at +8); x2 covers tile 16m+16.
    const uint32_t b4_off = (uint32_t)(lane & 15) * RSTRIDE + ((lane >> 4) << 4) + 32 * m;
    const uint32_t b2_off = (uint32_t)(lane & 15) * RSTRIDE + 32 * m + 32;

    // Loader per 32-c chunk (shift-only indexing):
    //   f2: 9r x 32c x 32 8B segs = 9216 tasks -> 36/thread
    //   f1 fp32: 32c x 32 float4 segs = 1024 tasks -> 4/thread
    auto issue = [&](int cc) {
        const int c0 = cc * 32;
        const uint32_t dbase = sb + (cc & 1) * BUFSZ;
        #pragma unroll
        for (int s = 0; s < 36; s++) {
            int t = tid + 256 * s;
            int r = t >> 10, ci = (t >> 5) & 31, sg = t & 31;
            int gr = h + r - 4;
            gr = gr < 0 ? 0 : (gr > NH - 1 ? NH - 1 : gr);   // clamp; invalid di never stored
            const __half* src = g_f2h + bbase + ((size_t)(c0 + ci) * NH + gr) * NW + 4 * sg;
            cpa8(dbase + r * F2RB + ci * RSTRIDE + 8 + 8 * sg, src);
        }
        #pragma unroll
        for (int s = 0; s < 4; s++) {
            int t = tid + 256 * s;
            int c2 = t >> 5, s2 = t & 31;
            const float* src = f1 + bbase + ((size_t)(c0 + c2) * NH + h) * NW + 4 * s2;
            cpa16(dbase + OFFF1 + c2 * (F1STR * 4) + 16 * s2, src);
        }
    };

    issue(0);
    asm volatile("cp.async.commit_group;");

    for (int cc = 0; cc < NCHUNK; cc++) {
        asm volatile("cp.async.wait_group 0;");   // chunk cc complete
        __syncthreads();
        if (cc + 1 < NCHUNK) issue(cc + 1);       // buf (cc+1)&1: consumed in cc-1, barrier passed
        asm volatile("cp.async.commit_group;");   // empty at tail keeps count uniform

        const uint32_t cbase = sb + (cc & 1) * BUFSZ;
        #pragma unroll
        for (int ks = 0; ks < 2; ks++) {          // two k16 steps per 32-c chunk
            const float* fp = reinterpret_cast<const float*>(
                smem + (cc & 1) * BUFSZ + OFFF1) + ks * 16 * F1STR + a_word0;
            uint32_t a0 = pkh2(fp[0],             fp[F1STR]);
            uint32_t a1 = pkh2(fp[8],             fp[F1STR + 8]);
            uint32_t a2 = pkh2(fp[8 * F1STR],     fp[9 * F1STR]);
            uint32_t a3 = pkh2(fp[8 * F1STR + 8], fp[9 * F1STR + 8]);
            const uint32_t kb = cbase + ks * 16 * RSTRIDE;
            #pragma unroll
            for (int r = 0; r < 9; r++) {
                const uint32_t rb = kb + r * F2RB;
                uint32_t q0, q1, q2, q3, e0, e1;
                ldsm4t(q0, q1, q2, q3, rb + b4_off);   // tiles 16m, 16m+8
                ldsm2t(e0, e1, rb + b2_off);           // tile 16m+16
                mma16816(acc[r][0], a0, a1, a2, a3, q0, q1);
                mma16816(acc[r][1], a0, a1, a2, a3, q2, q3);
                mma16816(acc[r][2], a0, a1, a2, a3, e0, e1);
            }
        }
    }

    // ---------------- epilogue: band extraction via per-warp staging ----------------
    __syncthreads();   // buffers dead; staging aliases them
    float* stage = reinterpret_cast<float*>(smem) + m * 16 * STAGE_W;
    const int l16 = lane & 15, dh = lane >> 4;
    #pragma unroll
    for (int r = 0; r < 9; r++) {
        #pragma unroll
        for (int t = 0; t < 3; t++) {
            stage[gid * STAGE_W + 8 * t + 2 * tig]           = acc[r][t][0];
            stage[gid * STAGE_W + 8 * t + 2 * tig + 1]       = acc[r][t][1];
            stage[(gid + 8) * STAGE_W + 8 * t + 2 * tig]     = acc[r][t][2];
            stage[(gid + 8) * STAGE_W + 8 * t + 2 * tig + 1] = acc[r][t][3];
        }
        __syncwarp();
        const int gr = h + r - 4;
        const bool valid = (gr >= 0 && gr < NH);
        // out[b, r*9+dj, h, 16m+l16] = band[l16][l16+dj] (padded-col space;
        // out-of-range w+dj-4 hit the zeroed halos)
        #pragma unroll
        for (int rd = 0; rd < 5; rd++) {
            int dj = 2 * rd + dh;
            if (dj < 9) {
                float v = valid ? stage[l16 * STAGE_W + l16 + dj] : 0.0f;
                out[(((size_t)b * ND + r * 9 + dj) * NH + h) * NW + 16 * m + l16] = v;
            }
        }
        __syncwarp();
    }
}

extern "C" void kernel_launch(void* const* d_in, const int* in_sizes, int n_in,
                              void* d_out, int out_size) {
    const float* f1 = (const float*)d_in[0];
    const float* f2 = (const float*)d_in[1];
    float* out = (float*)d_out;

    cudaFuncSetAttribute(corr_mma, cudaFuncAttributeMaxDynamicSharedMemorySize, SMEM_SZ);

    cast_kernel<<<4096, 256>>>((const float4*)f2);
    corr_mma<<<dim3(NH, NB), 256, SMEM_SZ>>>(f1, out);
}

// round 17
// speedup vs baseline: 1.1456x; 1.1456x over previous
#include <cuda_runtime.h>
#include <cuda_fp16.h>
#include <cstdint>

// Correlation layer via band-restricted mma.sync (m16n8k16 fp16, fp32 accum).
// out[b, di*9+dj, h, w] = sum_c f1[b,c,h,w] * f2[b,c,h+di-4,w+dj-4]
// B=8, C=256, H=64, W=128, D=81.
//
// R17 = R15 (best: R7 pipeline + fp32-f1 A-build + f2-only cast) with ONE
//       change: B tiles t0,t1 fetched by one ldmatrix.x4 (+ x2 for t2):
//       27 -> 18 LDSM ops per warp per chunk (lane mapping validated in
//       R9/R16 with identical rel_err).

#define NB 8
#define NC 256
#define NH 64
#define NW 128
#define ND 81

#define RSTRIDE 272                 // f2 smem c-row bytes (136 halves; %128==16 -> LDSM conflict-free)
#define F2ROW (16 * RSTRIDE)        // 4352 B per r per 16-c chunk
#define OFFF1 (9 * F2ROW)           // 39168
#define F1STR 132                   // f1 fp32 smem row stride in words (528 B)
#define F1SZ (16 * F1STR * 4)       // 8448 B
#define BUFSZ (OFFF1 + F1SZ)        // 47616
#define NBUF 4
#define SMEM_SZ (NBUF * BUFSZ)      // 190464 B
#define STAGE_W 25                  // floats per epilogue staging row

__device__ __half g_f2h[(size_t)NB * NC * NH * NW];

// ---------------- fp32 -> fp16 cast for f2 only (unpadded layout) ----------------
__global__ void cast_kernel(const float4* __restrict__ f2) {
    __half* dst = g_f2h;
    size_t i0 = (size_t)blockIdx.x * 1024 + threadIdx.x;
    #pragma unroll
    for (int k = 0; k < 4; k++) {
        size_t i = i0 + 256 * k;
        float4 v = f2[i];
        __half2 h0 = __floats2half2_rn(v.x, v.y);
        __half2 h1 = __floats2half2_rn(v.z, v.w);
        uint2 o;
        o.x = *reinterpret_cast<uint32_t*>(&h0);
        o.y = *reinterpret_cast<uint32_t*>(&h1);
        reinterpret_cast<uint2*>(dst)[i] = o;
    }
}

// ---------------- PTX helpers ----------------
__device__ __forceinline__ void cpa16(uint32_t dst, const void* src) {
    asm volatile("cp.async.ca.shared.global [%0], [%1], 16;" :: "r"(dst), "l"(src));
}
__device__ __forceinline__ void cpa8(uint32_t dst, const void* src) {
    asm volatile("cp.async.ca.shared.global [%0], [%1], 8;" :: "r"(dst), "l"(src));
}
__device__ __forceinline__ void ldsm4t(uint32_t& r0, uint32_t& r1,
                                       uint32_t& r2, uint32_t& r3, uint32_t a) {
    asm volatile("ldmatrix.sync.aligned.m8n8.x4.trans.shared.b16 {%0,%1,%2,%3}, [%4];"
                 : "=r"(r0), "=r"(r1), "=r"(r2), "=r"(r3) : "r"(a));
}
__device__ __forceinline__ void ldsm2t(uint32_t& r0, uint32_t& r1, uint32_t a) {
    asm volatile("ldmatrix.sync.aligned.m8n8.x2.trans.shared.b16 {%0,%1}, [%2];"
                 : "=r"(r0), "=r"(r1) : "r"(a));
}
__device__ __forceinline__ void mma16816(float* d, uint32_t a0, uint32_t a1,
                                         uint32_t a2, uint32_t a3,
                                         uint32_t b0, uint32_t b1) {
    asm volatile("mma.sync.aligned.m16n8k16.row.col.f32.f16.f16.f32 "
                 "{%0,%1,%2,%3}, {%4,%5,%6,%7}, {%8,%9}, {%0,%1,%2,%3};"
                 : "+f"(d[0]), "+f"(d[1]), "+f"(d[2]), "+f"(d[3])
                 : "r"(a0), "r"(a1), "r"(a2), "r"(a3), "r"(b0), "r"(b1));
}
__device__ __forceinline__ uint32_t pkh2(float lo, float hi) {
    __half2 h = __floats2half2_rn(lo, hi);
    return *reinterpret_cast<uint32_t*>(&h);
}

// ---------------- main kernel ----------------
__global__ void __launch_bounds__(256, 1)
corr_mma(const float* __restrict__ f1, float* __restrict__ out) {
    extern __shared__ char smem[];
    const uint32_t sb = (uint32_t)__cvta_generic_to_shared(smem);
    const int tid = threadIdx.x;
    const int lane = tid & 31, m = tid >> 5;    // warp = m16 w-block
    const int h = blockIdx.x, b = blockIdx.y;
    const size_t bbase = (size_t)b * NC * NH * NW;

    // Zero the f2 w-halos (cols 0-3 and 132-135 of each 272B c-row) in all
    // NBUF buffers; the 8B copies only ever write bytes [8, 264).
    for (int i = tid; i < NBUF * 9 * 16; i += 256) {
        int buf = i / 144, rr = i % 144;
        char* row = smem + buf * BUFSZ + rr * RSTRIDE;
        *reinterpret_cast<uint64_t*>(row) = 0ull;        // halves 0-3
        *reinterpret_cast<uint64_t*>(row + 264) = 0ull;  // halves 132-135
    }
    __syncthreads();

    float acc[9][3][4];
    #pragma unroll
    for (int r = 0; r < 9; r++)
        #pragma unroll
        for (int t = 0; t < 3; t++)
            #pragma unroll
            for (int k = 0; k < 4; k++)
                acc[r][t][k] = 0.0f;

    // A fragment source (f1 fp32 in smem, [k][w] with stride F1STR words):
    // rows 2tig(+1), 2tig+8(+1); cols 16m+gid, +8.
    const int gid = lane >> 2, tig = lane & 3;
    const uint32_t a_word0 = (uint32_t)(2 * tig) * F1STR + 16 * m + gid;
    // B (.trans): x4 covers tiles at padded cols 16m, 16m+8 (lanes 0-15 k-rows
    // at col base, lanes 16-31 at +8); x2 covers tile 16m+16.
    const uint32_t b4_off = (uint32_t)(lane & 15) * RSTRIDE + ((lane >> 4) << 4) + 32 * m;
    const uint32_t b2_off = (uint32_t)(lane & 15) * RSTRIDE + 32 * m + 32;

    // Loader per chunk (shift-only indexing):
    //   f2: 9r x 16c x 32 8B segs = 4608 tasks -> 18/thread
    //   f1 fp32: 16c x 32 float4 segs = 512 tasks -> 2/thread
    auto issue = [&](int cc) {
        const int c0 = cc * 16;
        const uint32_t dbase = sb + (cc & (NBUF - 1)) * BUFSZ;
        #pragma unroll
        for (int s = 0; s < 18; s++) {
            int t = tid + 256 * s;
            int r = t >> 9, ci = (t >> 5) & 15, sg = t & 31;
            int gr = h + r - 4;
            gr = gr < 0 ? 0 : (gr > NH - 1 ? NH - 1 : gr);   // clamp; invalid di never stored
            const __half* src = g_f2h + bbase + ((size_t)(c0 + ci) * NH + gr) * NW + 4 * sg;
            cpa8(dbase + r * F2ROW + ci * RSTRIDE + 8 + 8 * sg, src);
        }
        #pragma unroll
        for (int s = 0; s < 2; s++) {
            int t = tid + 256 * s;
            int c2 = t >> 5, s2 = t & 31;
            const float* src = f1 + bbase + ((size_t)(c0 + c2) * NH + h) * NW + 4 * s2;
            cpa16(dbase + OFFF1 + c2 * (F1STR * 4) + 16 * s2, src);
        }
    };

    // prologue: 3 chunks in flight
    #pragma unroll
    for (int p = 0; p < 3; p++) {
        issue(p);
        asm volatile("cp.async.commit_group;");
    }

    for (int cc = 0; cc < 16; cc++) {
        asm volatile("cp.async.wait_group 2;");   // chunk cc complete
        __syncthreads();
        if (cc + 3 < 16) issue(cc + 3);           // buf (cc+3)&3 == (cc-1)&3: consumed pre-barrier
        asm volatile("cp.async.commit_group;");   // empty at tail keeps count uniform

        const uint32_t cbase = sb + (cc & (NBUF - 1)) * BUFSZ;
        // Build A fragments from fp32 f1 (8 LDS.32 + 4 cvt-packs).
        const float* fp = reinterpret_cast<const float*>(
            smem + (cc & (NBUF - 1)) * BUFSZ + OFFF1) + a_word0;
        uint32_t a0 = pkh2(fp[0],             fp[F1STR]);
        uint32_t a1 = pkh2(fp[8],             fp[F1STR + 8]);
        uint32_t a2 = pkh2(fp[8 * F1STR],     fp[9 * F1STR]);
        uint32_t a3 = pkh2(fp[8 * F1STR + 8], fp[9 * F1STR + 8]);

        #pragma unroll
        for (int r = 0; r < 9; r++) {
            const uint32_t rb = cbase + r * F2ROW;
            uint32_t q0, q1, q2, q3, e0, e1;
            ldsm4t(q0, q1, q2, q3, rb + b4_off);   // tiles at cols 16m, 16m+8
            ldsm2t(e0, e1, rb + b2_off);           // tile at col 16m+16
            mma16816(acc[r][0], a0, a1, a2, a3, q0, q1);
            mma16816(acc[r][1], a0, a1, a2, a3, q2, q3);
            mma16816(acc[r][2], a0, a1, a2, a3, e0, e1);
        }
    }

    // ---------------- epilogue: band extraction via per-warp staging ----------------
    __syncthreads();   // buffers dead; staging aliases them
    float* stage = reinterpret_cast<float*>(smem) + m * 16 * STAGE_W;
    const int l16 = lane & 15, dh = lane >> 4;
    #pragma unroll
    for (int r = 0; r < 9; r++) {
        #pragma unroll
        for (int t = 0; t < 3; t++) {
            stage[gid * STAGE_W + 8 * t + 2 * tig]           = acc[r][t][0];
            stage[gid * STAGE_W + 8 * t + 2 * tig + 1]       = acc[r][t][1];
            stage[(gid + 8) * STAGE_W + 8 * t + 2 * tig]     = acc[r][t][2];
            stage[(gid + 8) * STAGE_W + 8 * t + 2 * tig + 1] = acc[r][t][3];
        }
        __syncwarp();
        const int gr = h + r - 4;
        const bool valid = (gr >= 0 && gr < NH);
        // out[b, r*9+dj, h, 16m+l16] = band[l16][l16+dj] (padded-col space;
        // out-of-range w+dj-4 hit the zeroed halos)
        #pragma unroll
        for (int rd = 0; rd < 5; rd++) {
            int dj = 2 * rd + dh;
            if (dj < 9) {
                float v = valid ? stage[l16 * STAGE_W + l16 + dj] : 0.0f;
                out[(((size_t)b * ND + r * 9 + dj) * NH + h) * NW + 16 * m + l16] = v;
            }
        }
        __syncwarp();
    }
}

extern "C" void kernel_launch(void* const* d_in, const int* in_sizes, int n_in,
                              void* d_out, int out_size) {
    const float* f1 = (const float*)d_in[0];
    const float* f2 = (const float*)d_in[1];
    float* out = (float*)d_out;

    cudaFuncSetAttribute(corr_mma, cudaFuncAttributeMaxDynamicSharedMemorySize, SMEM_SZ);

    cast_kernel<<<4096, 256>>>((const float4*)f2);
    corr_mma<<<dim3(NH, NB), 256, SMEM_SZ>>>(f1, out);
}